// round 13
// baseline (speedup 1.0000x reference)
#include <cuda_runtime.h>
#include <cuda_bf16.h>
#include <cstdint>

// PostProcessor3D: threshold(0.9) -> 5x5x5 maxpool(stride1,pad2) -> strict peak mask.
// In: [64,512,512] f32.  Out: [64,512,512] f32.
//
// BARRIER-FREE kernel: no shared memory, no __syncthreads, no cp.async.
// Each thread owns 4 W-cols x 1 H-row and loads its own 5 H-rows per plane
// straight from global (predicated LDG.128, immediate row offsets). The 4/5
// redundant row loads hit L1 (block plane working set = 12KB << 228KB); halo
// rows across blocks hit L2 (entire 64MB volume fits the 126MB L2).
// H-max in regs -> W-max via warp shuffles (boundary cols via predicated
// global float2 loads; covers both warp and tile boundaries) -> D via
// register rings marching 36 planes of a 32-deep D chunk.
//
// Raw-domain max (thr commutes with max; pads are 0). Threshold at emission:
//   out(od) = (cen==M3d && cen>THRESH) ? cen : 0,  cen = cen(p-2) ring slot.
//
// Block (64,8)=512 threads covers 256(W) x 8(H); grid 64x2x2 = 256 blocks,
// 2 blocks/SM (no smem; launch_bounds(512,2) targets 64 regs). 32 warps/SM
// with zero sync points -> continuous issue.

#define Wd 512
#define Hd 512
#define Dd 64
#define TW 256
#define TH 8
#define DCH 32
#define NP (DCH + 4)        // 36
#define PSZ (Hd * Wd)
#define THRESH 0.9f

__device__ __forceinline__ float4 fmax4(float4 a, float4 b) {
    return make_float4(fmaxf(a.x, b.x), fmaxf(a.y, b.y),
                       fmaxf(a.z, b.z), fmaxf(a.w, b.w));
}

__global__ __launch_bounds__(512, 2)
void peak3d_kernel(const float* __restrict__ in, float* __restrict__ out) {
    const int tx   = threadIdx.x;          // 0..63
    const int ty   = threadIdx.y;          // 0..7
    const int lane = tx & 31;
    const int h0   = blockIdx.x * TH;
    const int w0   = blockIdx.y * TW;
    const int d0   = blockIdx.z * DCH;

    const int c  = w0 + (tx << 2);         // 4 cols: c..c+3
    const int gh = h0 + ty;                // output row (always in range)

    // H-row validity (rows gh-2 .. gh+2)
    const bool ok0 = (gh >= 2);
    const bool ok1 = (gh >= 1);
    const bool ok3 = (gh + 1 < Hd);
    const bool ok4 = (gh + 2 < Hd);

    // warp/tile boundary handling: lanes 0/31 fetch the 2 missing neighbor
    // cols from global (zero at the true W edges)
    const bool edgeL    = (lane == 0)  && (c != 0);
    const bool edgeR    = (lane == 31) && (c + 4 != Wd);
    const bool haveEdge = edgeL || edgeR;
    const int  ec       = (lane == 0) ? (c - 2) : (c + 4);

    // base pointers at plane dl = d0-2 (may be logically out of range; loads
    // are predicated by dok so such pointers are never dereferenced)
    const float* gp = in + (long long)(d0 - 2) * PSZ + (size_t)gh * Wd + c;
    const float* ep = in + (long long)(d0 - 2) * PSZ + (size_t)gh * Wd + ec;

    // rings (raw domain)
    float4 z = make_float4(0.f, 0.f, 0.f, 0.f);
    float4 rp1 = z, rp2 = z, rp3 = z, rp4 = z;   // m2d(p-1..p-4)
    float4 cen1 = z, cen2 = z;                   // cen(p-1), cen(p-2)

    float* outp = out + (size_t)d0 * PSZ + (size_t)gh * Wd + c;

    #pragma unroll 2
    for (int p = 0; p < NP; ++p) {
        const int  dl  = d0 - 2 + p;
        const bool dok = ((unsigned)dl < (unsigned)Dd);

        // ---- load own 5 H-rows (4 cols each), predicated ----
        float4 t0 = z, t1 = z, t2 = z, t3 = z, t4 = z;
        if (dok) {
            t2 = *(const float4*)(gp);                       // own row, valid
            if (ok0) t0 = *(const float4*)(gp - 2 * Wd);
            if (ok1) t1 = *(const float4*)(gp - Wd);
            if (ok3) t3 = *(const float4*)(gp + Wd);
            if (ok4) t4 = *(const float4*)(gp + 2 * Wd);
        }
        float4 cen = t2;
        float4 hm  = fmax4(fmax4(fmax4(t0, t1), fmax4(t2, t3)), t4);

        // ---- boundary cols: H-max of 2 extension cols via global float2 ----
        float2 eh = make_float2(0.f, 0.f);
        if (haveEdge && dok) {
            float2 e0 = ok0 ? *(const float2*)(ep - 2 * Wd) : make_float2(0.f, 0.f);
            float2 e1 = ok1 ? *(const float2*)(ep - Wd)     : make_float2(0.f, 0.f);
            float2 e2 =       *(const float2*)(ep);
            float2 e3 = ok3 ? *(const float2*)(ep + Wd)     : make_float2(0.f, 0.f);
            float2 e4 = ok4 ? *(const float2*)(ep + 2 * Wd) : make_float2(0.f, 0.f);
            eh.x = fmaxf(fmaxf(fmaxf(e0.x, e1.x), fmaxf(e2.x, e3.x)), e4.x);
            eh.y = fmaxf(fmaxf(fmaxf(e0.y, e1.y), fmaxf(e2.y, e3.y)), e4.y);
        }

        // ---- W-max (window 5) via shuffles ----
        float l2 = __shfl_up_sync(0xffffffffu, hm.z, 1);
        float l1 = __shfl_up_sync(0xffffffffu, hm.w, 1);
        float r4 = __shfl_down_sync(0xffffffffu, hm.x, 1);
        float r5 = __shfl_down_sync(0xffffffffu, hm.y, 1);
        if (lane == 0)  { l2 = eh.x; l1 = eh.y; }   // 0 at global W edge
        if (lane == 31) { r4 = eh.x; r5 = eh.y; }

        float m01 = fmaxf(hm.x, hm.y);
        float m12 = fmaxf(hm.y, hm.z);
        float m23 = fmaxf(hm.z, hm.w);
        float4 m;                                   // m2d(p), raw
        m.x = fmaxf(fmaxf(l2, l1), fmaxf(m01, hm.z));
        m.y = fmaxf(l1, fmaxf(m01, m23));
        m.z = fmaxf(fmaxf(m01, m23), r4);
        m.w = fmaxf(fmaxf(m12, hm.w), fmaxf(r4, r5));

        // ---- emit plane od = d0 + (p-4): window m2d(p-4..p), center cen(p-2) ----
        if (p >= 4) {
            float4 M3 = fmax4(fmax4(fmax4(rp4, rp3), fmax4(rp2, rp1)), m);
            float4 o;
            o.x = (cen2.x == M3.x && cen2.x > THRESH) ? cen2.x : 0.f;
            o.y = (cen2.y == M3.y && cen2.y > THRESH) ? cen2.y : 0.f;
            o.z = (cen2.z == M3.z && cen2.z > THRESH) ? cen2.z : 0.f;
            o.w = (cen2.w == M3.w && cen2.w > THRESH) ? cen2.w : 0.f;
            *(float4*)outp = o;
            outp += PSZ;
        }

        rp4 = rp3; rp3 = rp2; rp2 = rp1; rp1 = m;
        cen2 = cen1; cen1 = cen;

        gp += PSZ;
        ep += PSZ;
    }
}

extern "C" void kernel_launch(void* const* d_in, const int* in_sizes, int n_in,
                              void* d_out, int out_size) {
    (void)in_sizes; (void)n_in; (void)out_size;
    const float* in = (const float*)d_in[0];
    float* out = (float*)d_out;

    dim3 block(64, 8);                       // 512 threads, 4 cols x 1 row each
    dim3 grid(Hd / TH, Wd / TW, Dd / DCH);   // 64 x 2 x 2 = 256 blocks
    peak3d_kernel<<<grid, block>>>(in, out);
}

// round 14
// speedup vs baseline: 1.0199x; 1.0199x over previous
#include <cuda_runtime.h>
#include <cuda_bf16.h>
#include <cstdint>

// PostProcessor3D: threshold(0.9) -> 5x5x5 maxpool(stride1,pad2) -> strict peak mask.
// In: [64,512,512] f32.  Out: [64,512,512] f32.
//
// BARRIER-FREE, SMEM-FREE, H-MARCHING kernel with register prefetch.
// Thread owns (d, cols c..c+3) and marches h. Per step: 5 planes (d-2..d+2)
// at row h are prefetched (previous iteration), folded by D-max -> dm, then
// W-max via warp shuffles (warp spans W at fixed d) -> wdm(h). The H window
// is handled by a 2-deep candidate ring (exact peak identity):
//   sv(h)  = (cen==wdm(h)) ? cen : 0
//   cn(h)  = (sv >= wdm(h-1) && sv >= wdm(h-2)) ? sv : 0
//   out(q) = (cn(q) > THRESH && cn(q) >= wdm(q+1) && cn(q) >= wdm(q+2)) ? cn(q) : 0
// Software pipeline: fold prefetch -> issue next row's loads -> compute.
// Pads are 0 (raw >= 0 after max vs -inf equivalence); threshold at emit.
//
// Block (128,2)=256 thr, launch_bounds(256,4) (64-reg cap), grid 32x16=512
// blocks -> one wave, ~28 warps/SM, ZERO sync points.

#define Wd 512
#define Hd 512
#define Dd 64
#define HCH 32              // output rows per block
#define NP (HCH + 4)        // 36 marched rows
#define PSZ (Hd * Wd)
#define THRESH 0.9f

__device__ __forceinline__ float4 fmax4(float4 a, float4 b) {
    return make_float4(fmaxf(a.x, b.x), fmaxf(a.y, b.y),
                       fmaxf(a.z, b.z), fmaxf(a.w, b.w));
}

__global__ __launch_bounds__(256, 4)
void peak3d_kernel(const float* __restrict__ in, float* __restrict__ out) {
    const int tx   = threadIdx.x;              // 0..127 (full W)
    const int ty   = threadIdx.y;              // 0..1
    const int lane = tx & 31;
    const int d    = blockIdx.x * 2 + ty;      // 0..63
    const int h0   = blockIdx.y * HCH;         // output rows h0..h0+31
    const int c    = tx << 2;

    // D-plane validity (planes d-2..d+2), constant over the march
    const bool ok0 = (d >= 2);
    const bool ok1 = (d >= 1);
    const bool ok3 = (d + 1 < Dd);
    const bool ok4 = (d + 2 < Dd);

    // warp-edge cols (W-max needs c-2,c-1 / c+4,c+5 on lanes 0/31)
    const bool edgeL    = (lane == 0);
    const bool haveEdge = (edgeL ? (c != 0) : (lane == 31 && c + 4 != Wd));
    const int  eofs     = edgeL ? -2 : 4;

    // single base pointer at plane d-2, row h0-2; 5 loads use imm offsets j*PSZ
    const float* p = in + (long long)(d - 2) * PSZ + (long long)(h0 - 2) * Wd + c;

    const float4 z  = make_float4(0.f, 0.f, 0.f, 0.f);
    const float2 z2 = make_float2(0.f, 0.f);

    // ---- prefetch row s=0 (h = h0-2) ----
    float4 n0 = z, n1 = z, n2 = z, n3 = z, n4 = z;
    float2 e0 = z2, e1 = z2, e2 = z2, e3 = z2, e4 = z2;
    {
        const bool hok = (h0 - 2 >= 0);        // top chunk only can be invalid
        if (hok) {
            if (ok0) n0 = *(const float4*)(p);
            if (ok1) n1 = *(const float4*)(p + PSZ);
                     n2 = *(const float4*)(p + 2 * PSZ);
            if (ok3) n3 = *(const float4*)(p + 3 * PSZ);
            if (ok4) n4 = *(const float4*)(p + 4 * PSZ);
            if (haveEdge) {
                const float* q = p + eofs;
                if (ok0) e0 = *(const float2*)(q);
                if (ok1) e1 = *(const float2*)(q + PSZ);
                         e2 = *(const float2*)(q + 2 * PSZ);
                if (ok3) e3 = *(const float2*)(q + 3 * PSZ);
                if (ok4) e4 = *(const float2*)(q + 4 * PSZ);
            }
        }
    }

    // rings: g1=wdm(h-1), g2=wdm(h-2); cnd1=cn(h-1), cnd0=cn(h-2)
    float4 g1 = z, g2 = z, cnd0 = z, cnd1 = z;

    float* outp = out + (size_t)d * PSZ + (size_t)h0 * Wd + c;

    #pragma unroll 4
    for (int s = 0; s < NP; ++s) {
        // ---- fold current prefetch: D-max + center + edge D-max ----
        float4 dm  = fmax4(fmax4(fmax4(n0, n1), fmax4(n2, n3)), n4);
        float4 cen = n2;
        float2 edm;
        edm.x = fmaxf(fmaxf(fmaxf(e0.x, e1.x), fmaxf(e2.x, e3.x)), e4.x);
        edm.y = fmaxf(fmaxf(fmaxf(e0.y, e1.y), fmaxf(e2.y, e3.y)), e4.y);

        // ---- issue next row's loads (consumed next iteration) ----
        p += Wd;
        n0 = z; n1 = z; n2 = z; n3 = z; n4 = z;
        e0 = z2; e1 = z2; e2 = z2; e3 = z2; e4 = z2;
        {
            const int hn = h0 - 1 + s;         // row for step s+1
            if (s + 1 < NP && (unsigned)hn < (unsigned)Hd) {
                if (ok0) n0 = *(const float4*)(p);
                if (ok1) n1 = *(const float4*)(p + PSZ);
                         n2 = *(const float4*)(p + 2 * PSZ);
                if (ok3) n3 = *(const float4*)(p + 3 * PSZ);
                if (ok4) n4 = *(const float4*)(p + 4 * PSZ);
                if (haveEdge) {
                    const float* q = p + eofs;
                    if (ok0) e0 = *(const float2*)(q);
                    if (ok1) e1 = *(const float2*)(q + PSZ);
                             e2 = *(const float2*)(q + 2 * PSZ);
                    if (ok3) e3 = *(const float2*)(q + 3 * PSZ);
                    if (ok4) e4 = *(const float2*)(q + 4 * PSZ);
                }
            }
        }

        // ---- W-max (window 5) via shuffles over D-maxed values ----
        float l2 = __shfl_up_sync(0xffffffffu, dm.z, 1);
        float l1 = __shfl_up_sync(0xffffffffu, dm.w, 1);
        float r4 = __shfl_down_sync(0xffffffffu, dm.x, 1);
        float r5 = __shfl_down_sync(0xffffffffu, dm.y, 1);
        if (lane == 0)  { l2 = edm.x; l1 = edm.y; }   // edm==0 at true W edge
        if (lane == 31) { r4 = edm.x; r5 = edm.y; }

        float m01 = fmaxf(dm.x, dm.y);
        float m12 = fmaxf(dm.y, dm.z);
        float m23 = fmaxf(dm.z, dm.w);
        float4 wdm;                                   // W/D max at row h
        wdm.x = fmaxf(fmaxf(l2, l1), fmaxf(m01, dm.z));
        wdm.y = fmaxf(l1, fmaxf(m01, m23));
        wdm.z = fmaxf(fmaxf(m01, m23), r4);
        wdm.w = fmaxf(fmaxf(m12, dm.w), fmaxf(r4, r5));

        // ---- emit output row ho = h0 + s - 4 (uses pre-update rings) ----
        if (s >= 4) {
            float4 o;
            o.x = (cnd0.x > THRESH && cnd0.x >= g1.x && cnd0.x >= wdm.x) ? cnd0.x : 0.f;
            o.y = (cnd0.y > THRESH && cnd0.y >= g1.y && cnd0.y >= wdm.y) ? cnd0.y : 0.f;
            o.z = (cnd0.z > THRESH && cnd0.z >= g1.z && cnd0.z >= wdm.z) ? cnd0.z : 0.f;
            o.w = (cnd0.w > THRESH && cnd0.w >= g1.w && cnd0.w >= wdm.w) ? cnd0.w : 0.f;
            *(float4*)outp = o;
            outp += Wd;
        }

        // ---- candidate for row h (uses g1=wdm(h-1), g2=wdm(h-2)) ----
        float4 sv, cn;
        sv.x = (cen.x == wdm.x) ? cen.x : 0.f;
        sv.y = (cen.y == wdm.y) ? cen.y : 0.f;
        sv.z = (cen.z == wdm.z) ? cen.z : 0.f;
        sv.w = (cen.w == wdm.w) ? cen.w : 0.f;
        cn.x = (sv.x >= g1.x && sv.x >= g2.x) ? sv.x : 0.f;
        cn.y = (sv.y >= g1.y && sv.y >= g2.y) ? sv.y : 0.f;
        cn.z = (sv.z >= g1.z && sv.z >= g2.z) ? sv.z : 0.f;
        cn.w = (sv.w >= g1.w && sv.w >= g2.w) ? sv.w : 0.f;

        cnd0 = cnd1; cnd1 = cn;
        g2   = g1;   g1   = wdm;
    }
}

extern "C" void kernel_launch(void* const* d_in, const int* in_sizes, int n_in,
                              void* d_out, int out_size) {
    (void)in_sizes; (void)n_in; (void)out_size;
    const float* in = (const float*)d_in[0];
    float* out = (float*)d_out;

    dim3 block(128, 2);                 // 256 threads: full W x 2 d's
    dim3 grid(Dd / 2, Hd / HCH);        // 32 x 16 = 512 blocks, one wave
    peak3d_kernel<<<grid, block>>>(in, out);
}

// round 15
// speedup vs baseline: 1.4320x; 1.4041x over previous
#include <cuda_runtime.h>
#include <cuda_bf16.h>
#include <cstdint>

// PostProcessor3D: threshold(0.9) -> 5x5x5 maxpool(stride1,pad2) -> strict peak mask.
// In: [64,512,512] f32.  Out: [64,512,512] f32.
//
// Champion R8 structure + streaming output stores + peeled no-emit iterations.
//
// Block (128,4)=512 threads, full W=512 (float4/thread) x 4 H rows, marching
// 36 planes of a 32-deep D chunk in PAIRS. Grid 128x2 = 256 blocks, 2 blocks
// co-resident per SM (launch_bounds(512,2), 96KB smem/block).
//
// Raw-domain max (thr commutes with max; pads are 0). Threshold at emission:
//   out(od) = (cen==M3d && cen>THRESH) ? cen : 0.
// Output written with __stcs (streaming) so the write-once output does not
// evict input planes from L2 (halo rows of neighboring blocks stay resident).
//
// RACE-FREE pair pipeline (NBUF=6, lookahead 2, issue before wait):
//   iter k (p=2k): issue p+2 -> buf (p+2)%6, p+3 -> (p+3)%6; wait_group 2
//   (p, p+1 complete); BAR; compute p, p+1.
// Safety: iter-k writes hit bufs (p-4)%6,(p-3)%6; the slowest concurrent
// reader (a k-1 laggard, bounded by BAR(k-1)) touches (p-2)%6,(p-1)%6 — disjoint.
// Off-range planes commit EMPTY groups (no writes).

#define Wd 512
#define Hd 512
#define Dd 64
#define TH 4
#define LR 8
#define DCH 32
#define NP (DCH + 4)        // 36 (even)
#define PSZ (Hd * Wd)
#define THRESH 0.9f
#define BUFSZ (LR * Wd)     // 4096 floats per buffer
#define NBUF 6

__device__ __forceinline__ void cp_async16(uint32_t dst, const void* src, int src_bytes) {
    asm volatile("cp.async.cg.shared.global [%0], [%1], 16, %2;\n"
                 :: "r"(dst), "l"(src), "r"(src_bytes));
}
__device__ __forceinline__ void cp_commit() {
    asm volatile("cp.async.commit_group;\n");
}
__device__ __forceinline__ void cp_wait2() {
    asm volatile("cp.async.wait_group 2;\n");
}
__device__ __forceinline__ void cp_wait0() {
    asm volatile("cp.async.wait_group 0;\n");
}

__device__ __forceinline__ float4 fmax4(float4 a, float4 b) {
    return make_float4(fmaxf(a.x, b.x), fmaxf(a.y, b.y),
                       fmaxf(a.z, b.z), fmaxf(a.w, b.w));
}

extern __shared__ float vsm[];   // [NBUF][LR][512] raw planes

__global__ __launch_bounds__(512, 2)
void peak3d_kernel(const float* __restrict__ in, float* __restrict__ out) {
    const int tx   = threadIdx.x;          // 0..127
    const int ty   = threadIdx.y;          // 0..3
    const int lane = tx & 31;
    const int c    = tx << 2;
    const int h0   = blockIdx.x * TH;
    const int d0   = blockIdx.y * DCH;

    const bool edgeL    = (lane == 0);
    const bool edgeR    = (lane == 31);
    const bool haveEdge = (edgeL && tx != 0) || (edgeR && tx != 127);
    const int  ec       = edgeL ? (c - 2) : (c + 4);

    // this thread copies loaded-rows ty and ty+4 of strip [h0-2, h0+5]
    const int  k2  = ty + 4;
    const int  gh1 = h0 - 2 + ty;
    const int  gh2 = h0 + 2 + ty;
    const bool ok1 = ((unsigned)gh1 < (unsigned)Hd);
    const bool ok2 = (gh2 < Hd);

    const float* g1 = in + (size_t)(ok1 ? gh1 : 0) * Wd + c;
    const float* g2 = in + (size_t)(ok2 ? gh2 : 0) * Wd + c;

    const uint32_t sbase = (uint32_t)__cvta_generic_to_shared(vsm);
    const uint32_t dst1  = sbase + (uint32_t)(ty * Wd + c) * 4u;
    const uint32_t dst2  = sbase + (uint32_t)(k2 * Wd + c) * 4u;
    const uint32_t BUFB  = BUFSZ * 4u;

    // issue async copies for plane pf (dl = d0-2+pf) into buf pf%NBUF.
    // pf >= NP: EMPTY commit group (keeps wait counts aligned, no writes).
    auto issue = [&](int pf) {
        if (pf < NP) {
            int  dl  = d0 - 2 + pf;
            bool dok = ((unsigned)dl < (unsigned)Dd);
            int  dlc = dok ? dl : 0;
            uint32_t boff = (uint32_t)(pf % NBUF) * BUFB;
            cp_async16(dst1 + boff, g1 + (size_t)dlc * PSZ, (ok1 && dok) ? 16 : 0);
            cp_async16(dst2 + boff, g2 + (size_t)dlc * PSZ, (ok2 && dok) ? 16 : 0);
        }
        cp_commit();
    };

    issue(0);
    issue(1);

    // rings (raw domain)
    float4 rp1 = make_float4(0.f, 0.f, 0.f, 0.f);
    float4 rp2 = rp1, rp3 = rp1, rp4 = rp1;          // m2d(p-1..p-4)
    float4 cen1 = rp1, cen2 = rp1;                   // cen(p-1), cen(p-2)

    float* outp = out + (size_t)d0 * PSZ + (size_t)(h0 + ty) * Wd + c;

    // compute one plane from buffer vb; ring update + optional emit
    auto plane = [&](const float* vb, bool emit) {
        const float* vr = vb + ty * Wd + c;
        float4 t0 = *(const float4*)(vr);
        float4 t1 = *(const float4*)(vr + 512);
        float4 t2 = *(const float4*)(vr + 1024);   // center row
        float4 t3 = *(const float4*)(vr + 1536);
        float4 t4 = *(const float4*)(vr + 2048);
        float4 cen = t2;
        float4 hm  = fmax4(fmax4(fmax4(t0, t1), fmax4(t2, t3)), t4);

        float2 eh = make_float2(0.f, 0.f);
        if (haveEdge) {
            const float* ep = vb + ty * Wd + ec;
            float2 e0 = *(const float2*)(ep);
            float2 e1 = *(const float2*)(ep + 512);
            float2 e2 = *(const float2*)(ep + 1024);
            float2 e3 = *(const float2*)(ep + 1536);
            float2 e4 = *(const float2*)(ep + 2048);
            eh.x = fmaxf(fmaxf(fmaxf(e0.x, e1.x), fmaxf(e2.x, e3.x)), e4.x);
            eh.y = fmaxf(fmaxf(fmaxf(e0.y, e1.y), fmaxf(e2.y, e3.y)), e4.y);
        }

        float l2 = __shfl_up_sync(0xffffffffu, hm.z, 1);
        float l1 = __shfl_up_sync(0xffffffffu, hm.w, 1);
        float r4 = __shfl_down_sync(0xffffffffu, hm.x, 1);
        float r5 = __shfl_down_sync(0xffffffffu, hm.y, 1);
        if (edgeL) { l2 = eh.x; l1 = eh.y; }   // 0 at global W edge
        if (edgeR) { r4 = eh.x; r5 = eh.y; }

        float m01 = fmaxf(hm.x, hm.y);
        float m12 = fmaxf(hm.y, hm.z);
        float m23 = fmaxf(hm.z, hm.w);
        float4 m;                               // m2d(p), raw
        m.x = fmaxf(fmaxf(l2, l1), fmaxf(m01, hm.z));
        m.y = fmaxf(l1, fmaxf(m01, m23));
        m.z = fmaxf(fmaxf(m01, m23), r4);
        m.w = fmaxf(fmaxf(m12, hm.w), fmaxf(r4, r5));

        if (emit) {
            float4 M3 = fmax4(fmax4(fmax4(rp4, rp3), fmax4(rp2, rp1)), m);
            float4 o;
            o.x = (cen2.x == M3.x && cen2.x > THRESH) ? cen2.x : 0.f;
            o.y = (cen2.y == M3.y && cen2.y > THRESH) ? cen2.y : 0.f;
            o.z = (cen2.z == M3.z && cen2.z > THRESH) ? cen2.z : 0.f;
            o.w = (cen2.w == M3.w && cen2.w > THRESH) ? cen2.w : 0.f;
            __stcs((float4*)outp, o);           // streaming: don't pollute L2
            outp += PSZ;
        }

        rp4 = rp3; rp3 = rp2; rp2 = rp1; rp1 = m;
        cen2 = cen1; cen1 = cen;
    };

    // ---- peeled: k=0,1 (planes 0..3), no emission ----
    #pragma unroll
    for (int k = 0; k < 2; ++k) {
        const int p = 2 * k;
        issue(p + 2);
        issue(p + 3);
        cp_wait2();
        __syncthreads();
        plane(vsm + ( p      % NBUF) * BUFSZ, false);
        plane(vsm + ((p + 1) % NBUF) * BUFSZ, false);
    }

    // ---- steady state: k=2..17, always emit ----
    #pragma unroll 2
    for (int k = 2; k < NP / 2; ++k) {
        const int p = 2 * k;
        issue(p + 2);       // -> buf (p-4)%6 ; slowest reader at (p-2),(p-1): disjoint
        issue(p + 3);       // -> buf (p-3)%6
        cp_wait2();         // planes p, p+1 complete
        __syncthreads();    // all threads' copies of p, p+1 visible
        plane(vsm + ( p      % NBUF) * BUFSZ, true);
        plane(vsm + ((p + 1) % NBUF) * BUFSZ, true);
    }

    cp_wait0();   // drain trailing groups before exit
}

extern "C" void kernel_launch(void* const* d_in, const int* in_sizes, int n_in,
                              void* d_out, int out_size) {
    (void)in_sizes; (void)n_in; (void)out_size;
    const float* in = (const float*)d_in[0];
    float* out = (float*)d_out;

    const int smem_bytes = NBUF * BUFSZ * (int)sizeof(float);   // 98304
    cudaFuncSetAttribute(peak3d_kernel,
                         cudaFuncAttributeMaxDynamicSharedMemorySize, smem_bytes);

    dim3 block(128, 4);                 // 512 threads
    dim3 grid(Hd / TH, Dd / DCH);       // 128 x 2 = 256 blocks (2/SM resident)
    peak3d_kernel<<<grid, block, smem_bytes>>>(in, out);
}